// round 15
// baseline (speedup 1.0000x reference)
#include <cuda_runtime.h>
#include <cuda_bf16.h>
#include <cstdint>

#define N_NODES 50000
#define F_IN    128
#define F_HID   512
#define CAP     128            // fixed bucket capacity per node
#define MAX_OVF 4096           // overflow list capacity (never used in practice)

// ---------------------------------------------------------------------------
// Scratch (__device__ globals; allocation-free rule)
// Self-maintaining invariants: g_cur zeroed by gather tail, g_ovf_cnt by MLP
// block 0. Initial state is static zero.
// ---------------------------------------------------------------------------
__device__ __align__(16) __nv_bfloat16 g_h0_hi[N_NODES * F_IN];       // split h0
__device__ __align__(16) __nv_bfloat16 g_h0_lo[N_NODES * F_IN];
__device__ __align__(16) __nv_bfloat16 g_w1t_hi[F_HID * F_IN];        // W1^T split [512,128]
__device__ __align__(16) __nv_bfloat16 g_w1t_lo[F_HID * F_IN];
__device__ __align__(16) __nv_bfloat16 g_w2t_hi[F_IN * F_HID];        // W2^T split [128,512]
__device__ __align__(16) __nv_bfloat16 g_w2t_lo[F_IN * F_HID];
__device__ int g_cur[N_NODES];                 // per-node fill counters (=degree)
__device__ int g_bucket[N_NODES * CAP];        // fixed-capacity buckets of src ids
__device__ int g_ovf[2 * MAX_OVF];             // overflow (src,dst) pairs
__device__ int g_ovf_cnt;

__device__ __forceinline__ uint32_t smem_to_u32(const void* p) {
    uint32_t a;
    asm("{ .reg .u64 t; cvta.to.shared.u64 t, %1; cvt.u32.u64 %0, t; }"
        : "=r"(a) : "l"(p));
    return a;
}
__device__ __forceinline__ uint32_t pack_bf2(__nv_bfloat16 a, __nv_bfloat16 b) {
    __nv_bfloat162 t(a, b);
    return *reinterpret_cast<uint32_t*>(&t);
}
__device__ __forceinline__ uint32_t sw128(uint32_t byte_off) {
    return byte_off ^ ((byte_off >> 3) & 0x70);
}
// 64x128 bf16 tile (A tile, W1 chunk): two 64x64 column blocks (8KB each)
__device__ __forceinline__ uint32_t t64r(int r, int k) {
    return (uint32_t)((k >> 6) * 8192) + sw128((uint32_t)(r * 128 + (k & 63) * 2));
}
// Nx64 bf16 tile (H: 64 rows; W2 chunk: 128 rows): single block, 128B rows
__device__ __forceinline__ uint32_t t64c(int r, int k) {
    return sw128((uint32_t)(r * 128 + k * 2));
}

__device__ __forceinline__ void ldmx4(uint32_t* r, uint32_t addr) {
    asm volatile("ldmatrix.sync.aligned.m8n8.x4.shared.b16 {%0,%1,%2,%3}, [%4];"
                 : "=r"(r[0]), "=r"(r[1]), "=r"(r[2]), "=r"(r[3]) : "r"(addr));
}
__device__ __forceinline__ void mma16816(float* c, const uint32_t* a, const uint32_t* b) {
    asm volatile(
        "mma.sync.aligned.m16n8k16.row.col.f32.bf16.bf16.f32 "
        "{%0,%1,%2,%3}, {%4,%5,%6,%7}, {%8,%9}, {%0,%1,%2,%3};"
        : "+f"(c[0]), "+f"(c[1]), "+f"(c[2]), "+f"(c[3])
        : "r"(a[0]), "r"(a[1]), "r"(a[2]), "r"(a[3]), "r"(b[0]), "r"(b[1]));
}
#define CP_ASYNC16(dst_u32, src_ptr) \
    asm volatile("cp.async.cg.shared.global [%0], [%1], 16;" \
                 :: "r"(dst_u32), "l"(src_ptr) : "memory")
#define CP_COMMIT() asm volatile("cp.async.commit_group;" ::: "memory")
#define CP_WAIT1()  asm volatile("cp.async.wait_group 1;"  ::: "memory")

// ---------------------------------------------------------------------------
// Kernel 1 (prep): heterogeneous grid.
//   blocks [0, nb_bucket)          : bucket edges by dst (per-block dtype detect)
//   blocks [nb_bucket, +256)       : W1 transpose+split
//   blocks [nb_bucket+256, +512)   : W2 transpose+split
// ---------------------------------------------------------------------------
__global__ __launch_bounds__(256)
void prep_kernel(const void* __restrict__ ei, int n_edges, int nb_bucket,
                 const float* __restrict__ W1, const float* __restrict__ W2)
{
    const int b = blockIdx.x;
    const int tid = threadIdx.x;

    if (b < nb_bucket) {
        __shared__ int s_is64;
        if (tid < 32) {
            const int* w = (const int*)ei;
            int nz = (w[2 * tid + 1] != 0) | (w[2 * (tid + 32) + 1] != 0);
            unsigned any = __ballot_sync(0xffffffff, nz);
            if (tid == 0) s_is64 = (any == 0) ? 1 : 0;
        }
        __syncthreads();
        const int is64 = s_is64;

        int base = b * 1024;
        #pragma unroll
        for (int k = 0; k < 4; k++) {
            int e = base + k * 256 + tid;
            if (e < n_edges) {
                int s, d;
                if (is64) {
                    s = (int)((const long long*)ei)[e];
                    d = (int)((const long long*)ei)[n_edges + e];
                } else {
                    s = ((const int*)ei)[e];
                    d = ((const int*)ei)[n_edges + e];
                }
                if (s >= 0 && s < N_NODES && d >= 0 && d < N_NODES) {
                    int pos = atomicAdd(&g_cur[d], 1);
                    if (pos < CAP) {
                        g_bucket[d * CAP + pos] = s;
                    } else {
                        int o = atomicAdd(&g_ovf_cnt, 1);
                        if (o < MAX_OVF) {
                            g_ovf[2 * o] = s;
                            g_ovf[2 * o + 1] = d;
                        }
                    }
                }
            }
        }
    } else if (b < nb_bucket + 256) {
        int idx = (b - nb_bucket) * 256 + tid;     // < 65536
        int n = idx / F_IN, k = idx % F_IN;
        float v = W1[(size_t)k * F_HID + n];
        __nv_bfloat16 h = __float2bfloat16(v);
        g_w1t_hi[idx] = h;
        g_w1t_lo[idx] = __float2bfloat16(v - __bfloat162float(h));
    } else {
        int idx = (b - nb_bucket - 256) * 256 + tid;
        int n = idx / F_HID, k = idx % F_HID;
        float v = W2[(size_t)k * F_IN + n];
        __nv_bfloat16 h = __float2bfloat16(v);
        g_w2t_hi[idx] = h;
        g_w2t_lo[idx] = __float2bfloat16(v - __bfloat162float(h));
    }
}

// ---------------------------------------------------------------------------
// Kernel 2: gather-accumulate, warp per node, lane-parallel index loads.
// Inline overflow handling (scan g_ovf for dst==node; cnt==0 in practice).
// Tail: reset g_cur[node] = 0.
// ---------------------------------------------------------------------------
__global__ __launch_bounds__(256)
void gather_kernel(const float* __restrict__ x,
                   const float* __restrict__ eps,
                   __nv_bfloat16* __restrict__ h_hi,
                   __nv_bfloat16* __restrict__ h_lo)
{
    const int warp = (blockIdx.x * blockDim.x + threadIdx.x) >> 5;
    if (warp >= N_NODES) return;
    const int lane = threadIdx.x & 31;

    const int deg  = min(g_cur[warp], CAP);
    const int base = warp * CAP;
    const float s = 1.0f + *eps;

    float4 xv = *reinterpret_cast<const float4*>(x + (size_t)warp * F_IN + lane * 4);
    float4 a0, a1, a2, a3;
    a0.x = xv.x * s; a0.y = xv.y * s; a0.z = xv.z * s; a0.w = xv.w * s;
    a1 = make_float4(0.f, 0.f, 0.f, 0.f);
    a2 = make_float4(0.f, 0.f, 0.f, 0.f);
    a3 = make_float4(0.f, 0.f, 0.f, 0.f);

    for (int b = 0; b < deg; b += 32) {
        const int n = min(32, deg - b);
        int idx = (b + lane < deg) ? g_bucket[base + b + lane] : 0;
        int j = 0;
        for (; j + 3 < n; j += 4) {
            int s0 = __shfl_sync(0xffffffff, idx, j);
            int s1 = __shfl_sync(0xffffffff, idx, j + 1);
            int s2 = __shfl_sync(0xffffffff, idx, j + 2);
            int s3 = __shfl_sync(0xffffffff, idx, j + 3);
            float4 v0 = *reinterpret_cast<const float4*>(x + (size_t)s0 * F_IN + lane * 4);
            float4 v1 = *reinterpret_cast<const float4*>(x + (size_t)s1 * F_IN + lane * 4);
            float4 v2 = *reinterpret_cast<const float4*>(x + (size_t)s2 * F_IN + lane * 4);
            float4 v3 = *reinterpret_cast<const float4*>(x + (size_t)s3 * F_IN + lane * 4);
            a0.x += v0.x; a0.y += v0.y; a0.z += v0.z; a0.w += v0.w;
            a1.x += v1.x; a1.y += v1.y; a1.z += v1.z; a1.w += v1.w;
            a2.x += v2.x; a2.y += v2.y; a2.z += v2.z; a2.w += v2.w;
            a3.x += v3.x; a3.y += v3.y; a3.z += v3.z; a3.w += v3.w;
        }
        for (; j < n; j++) {
            int s0 = __shfl_sync(0xffffffff, idx, j);
            float4 v0 = *reinterpret_cast<const float4*>(x + (size_t)s0 * F_IN + lane * 4);
            a0.x += v0.x; a0.y += v0.y; a0.z += v0.z; a0.w += v0.w;
        }
    }

    // inline overflow: cnt == 0 in practice (single broadcast read)
    {
        const int cnt = min(g_ovf_cnt, MAX_OVF);
        for (int e = 0; e < cnt; e++) {
            if (g_ovf[2 * e + 1] == warp) {
                int s0 = g_ovf[2 * e];
                float4 v0 = *reinterpret_cast<const float4*>(x + (size_t)s0 * F_IN + lane * 4);
                a0.x += v0.x; a0.y += v0.y; a0.z += v0.z; a0.w += v0.w;
            }
        }
    }

    a0.x += a1.x + a2.x + a3.x;
    a0.y += a1.y + a2.y + a3.y;
    a0.z += a1.z + a2.z + a3.z;
    a0.w += a1.w + a2.w + a3.w;

    __nv_bfloat16 h0b = __float2bfloat16(a0.x);
    __nv_bfloat16 h1b = __float2bfloat16(a0.y);
    __nv_bfloat16 h2b = __float2bfloat16(a0.z);
    __nv_bfloat16 h3b = __float2bfloat16(a0.w);
    uint2 hv, lv;
    hv.x = pack_bf2(h0b, h1b);
    hv.y = pack_bf2(h2b, h3b);
    lv.x = pack_bf2(__float2bfloat16(a0.x - __bfloat162float(h0b)),
                    __float2bfloat16(a0.y - __bfloat162float(h1b)));
    lv.y = pack_bf2(__float2bfloat16(a0.z - __bfloat162float(h2b)),
                    __float2bfloat16(a0.w - __bfloat162float(h3b)));
    *reinterpret_cast<uint2*>(h_hi + (size_t)warp * F_IN + lane * 4) = hv;
    *reinterpret_cast<uint2*>(h_lo + (size_t)warp * F_IN + lane * 4) = lv;

    if (lane == 0) g_cur[warp] = 0;
}

// ---------------------------------------------------------------------------
// Fused MLP, BM=64, occupancy 2, cp.async double-buffered weights.
// B fragments loaded pairwise via ldmatrix.x4 (regs r0,r1 -> nt; r2,r3 -> nt+1;
// lane mapping row = n0 + ((lane>>4)<<3) + (lane&7), khalf = (lane>>3)&1).
// ---------------------------------------------------------------------------
__global__ __launch_bounds__(256, 2)
void fused_mlp_kernel(const __nv_bfloat16* __restrict__ A_hi,
                      const __nv_bfloat16* __restrict__ A_lo,
                      const __nv_bfloat16* __restrict__ W1t_hi,
                      const __nv_bfloat16* __restrict__ W1t_lo,
                      const float* __restrict__ b1,
                      const __nv_bfloat16* __restrict__ W2t_hi,
                      const __nv_bfloat16* __restrict__ W2t_lo,
                      const float* __restrict__ b2,
                      float* __restrict__ out,
                      int M)
{
    constexpr int SM_A_HI  = 0;
    constexpr int SM_A_LO  = 16384;
    constexpr int SM_H_HI  = 32768;
    constexpr int SM_H_LO  = 40960;
    constexpr int SM_W1_HI = 49152;
    constexpr int SM_W1_LO = 65536;
    constexpr int SM_W2_HI = 81920;
    constexpr int SM_W2_LO = 98304;

    extern __shared__ __align__(1024) char smem[];
    const uint32_t sbase = smem_to_u32(smem);

    const int tid  = threadIdx.x;
    const int wid  = tid >> 5;
    const int lane = tid & 31;
    const int bm   = blockIdx.x * 64;

    if (blockIdx.x == 0 && tid == 0) g_ovf_cnt = 0;   // reset for next run

    const int wm = wid >> 2;
    const int wn = wid & 3;

    const int a_row = lane & 15;
    const int a_kh  = (lane >> 4) & 1;
    // paired-B ldmx4 lane mapping
    const int bq_row = ((lane >> 4) << 3) + (lane & 7);   // 0..15
    const int bq_kh  = (lane >> 3) & 1;
    const int er    = lane >> 2;
    const int ec    = (lane & 3) * 2;

    {
        #pragma unroll
        for (int it = 0; it < 4; it++) {
            int slot = tid + it * 256;
            int r  = slot >> 4;
            int c8 = slot & 15;
            uint32_t off = t64r(r, c8 * 8);
            CP_ASYNC16(sbase + SM_W1_HI + off, W1t_hi + (size_t)r * F_IN + c8 * 8);
            CP_ASYNC16(sbase + SM_W1_LO + off, W1t_lo + (size_t)r * F_IN + c8 * 8);
        }
        CP_COMMIT();
    }

    #pragma unroll
    for (int it = 0; it < 4; it++) {
        int slot = tid + it * 256;
        int r  = slot >> 4;
        int c8 = slot & 15;
        int gr = bm + r;
        uint4 hv, lv;
        if (gr < M) {
            hv = *reinterpret_cast<const uint4*>(A_hi + (size_t)gr * F_IN + c8 * 8);
            lv = *reinterpret_cast<const uint4*>(A_lo + (size_t)gr * F_IN + c8 * 8);
        } else {
            hv = make_uint4(0, 0, 0, 0); lv = make_uint4(0, 0, 0, 0);
        }
        uint32_t off = t64r(r, c8 * 8);
        *reinterpret_cast<uint4*>(smem + SM_A_HI + off) = hv;
        *reinterpret_cast<uint4*>(smem + SM_A_LO + off) = lv;
    }

    float acc_out[2][4][4];
    #pragma unroll
    for (int i = 0; i < 2; i++)
        #pragma unroll
        for (int j = 0; j < 4; j++)
            #pragma unroll
            for (int q = 0; q < 4; q++)
                acc_out[i][j][q] = 0.f;

    for (int c = 0; c < 8; c++) {
        __syncthreads();

        #pragma unroll
        for (int it = 0; it < 4; it++) {
            int slot = tid + it * 256;
            int r  = slot >> 3;
            int c8 = slot & 7;
            uint32_t off = t64c(r, c8 * 8);
            const size_t g = (size_t)r * F_HID + c * 64 + c8 * 8;
            CP_ASYNC16(sbase + SM_W2_HI + off, W2t_hi + g);
            CP_ASYNC16(sbase + SM_W2_LO + off, W2t_lo + g);
        }
        CP_COMMIT();
        CP_WAIT1();
        __syncthreads();

        // ---- GEMM1: H = A @ W1c  (out 64x64, K=128), warp tile 32x16 ----
        float acc_h[2][2][4];
        #pragma unroll
        for (int i = 0; i < 2; i++)
            #pragma unroll
            for (int j = 0; j < 2; j++)
                #pragma unroll
                for (int q = 0; q < 4; q++)
                    acc_h[i][j][q] = 0.f;

        #pragma unroll
        for (int ks = 0; ks < 8; ks++) {
            uint32_t bh[4], bl[4];     // [2nt+reg]: frag nt = (bh[2nt], bh[2nt+1])
            {
                uint32_t off = t64r(wn * 16 + bq_row, ks * 16 + bq_kh * 8);
                ldmx4(bh, sbase + SM_W1_HI + off);
                ldmx4(bl, sbase + SM_W1_LO + off);
            }
            #pragma unroll
            for (int mt = 0; mt < 2; mt++) {
                int m = wm * 32 + mt * 16 + a_row;
                uint32_t off = t64r(m, ks * 16 + a_kh * 8);
                uint32_t ah[4], al[4];
                ldmx4(ah, sbase + SM_A_HI + off);
                ldmx4(al, sbase + SM_A_LO + off);
                #pragma unroll
                for (int nt = 0; nt < 2; nt++) {
                    mma16816(acc_h[mt][nt], ah, bh + 2 * nt);
                    mma16816(acc_h[mt][nt], ah, bl + 2 * nt);
                    mma16816(acc_h[mt][nt], al, bh + 2 * nt);
                }
            }
        }
        __syncthreads();

        if (c + 1 < 8) {
            #pragma unroll
            for (int it = 0; it < 4; it++) {
                int slot = tid + it * 256;
                int r  = slot >> 4;
                int c8 = slot & 15;
                uint32_t off = t64r(r, c8 * 8);
                const size_t g = (size_t)((c + 1) * 64 + r) * F_IN + c8 * 8;
                CP_ASYNC16(sbase + SM_W1_HI + off, W1t_hi + g);
                CP_ASYNC16(sbase + SM_W1_LO + off, W1t_lo + g);
            }
        }
        CP_COMMIT();

        #pragma unroll
        for (int mt = 0; mt < 2; mt++) {
            int lr0 = wm * 32 + mt * 16 + er;
            #pragma unroll
            for (int nt = 0; nt < 2; nt++) {
                int lc = wn * 16 + nt * 8 + ec;
                float bia0 = b1[c * 64 + lc];
                float bia1 = b1[c * 64 + lc + 1];
                #pragma unroll
                for (int h = 0; h < 2; h++) {
                    float v0 = fmaxf(acc_h[mt][nt][2 * h + 0] + bia0, 0.f);
                    float v1 = fmaxf(acc_h[mt][nt][2 * h + 1] + bia1, 0.f);
                    __nv_bfloat16 hh0 = __float2bfloat16(v0);
                    __nv_bfloat16 hh1 = __float2bfloat16(v1);
                    uint32_t off = t64c(lr0 + h * 8, lc);
                    *reinterpret_cast<uint32_t*>(smem + SM_H_HI + off) = pack_bf2(hh0, hh1);
                    *reinterpret_cast<uint32_t*>(smem + SM_H_LO + off) =
                        pack_bf2(__float2bfloat16(v0 - __bfloat162float(hh0)),
                                 __float2bfloat16(v1 - __bfloat162float(hh1)));
                }
            }
        }
        CP_WAIT1();
        __syncthreads();

        // ---- GEMM2: out += H @ W2c  (out 64x128, K=64), warp tile 32x32 ----
        #pragma unroll
        for (int ks = 0; ks < 4; ks++) {
            uint32_t bh[8], bl[8];     // frag nt = (bh[2nt], bh[2nt+1])
            #pragma unroll
            for (int p = 0; p < 2; p++) {
                uint32_t off = t64c(wn * 32 + p * 16 + bq_row, ks * 16 + bq_kh * 8);
                ldmx4(bh + 4 * p, sbase + SM_W2_HI + off);
                ldmx4(bl + 4 * p, sbase + SM_W2_LO + off);
            }
            #pragma unroll
            for (int mt = 0; mt < 2; mt++) {
                int m = wm * 32 + mt * 16 + a_row;
                uint32_t off = t64c(m, ks * 16 + a_kh * 8);
                uint32_t ah[4], al[4];
                ldmx4(ah, sbase + SM_H_HI + off);
                ldmx4(al, sbase + SM_H_LO + off);
                #pragma unroll
                for (int nt = 0; nt < 4; nt++) {
                    mma16816(acc_out[mt][nt], ah, bh + 2 * nt);
                    mma16816(acc_out[mt][nt], ah, bl + 2 * nt);
                    mma16816(acc_out[mt][nt], al, bh + 2 * nt);
                }
            }
        }
    }

    #pragma unroll
    for (int mt = 0; mt < 2; mt++) {
        const int row0 = bm + wm * 32 + mt * 16 + er;
        #pragma unroll
        for (int nt = 0; nt < 4; nt++) {
            const int col = wn * 32 + nt * 8 + ec;
            const float bia0 = b2[col], bia1 = b2[col + 1];
            #pragma unroll
            for (int h = 0; h < 2; h++) {
                const int row = row0 + h * 8;
                if (row >= M) continue;
                float2 v;
                v.x = acc_out[mt][nt][2 * h + 0] + bia0;
                v.y = acc_out[mt][nt][2 * h + 1] + bia1;
                *reinterpret_cast<float2*>(out + (size_t)row * F_IN + col) = v;
            }
        }
    }
}

// ---------------------------------------------------------------------------
// Launch
// ---------------------------------------------------------------------------
extern "C" void kernel_launch(void* const* d_in, const int* in_sizes, int n_in,
                              void* d_out, int out_size)
{
    const float* x   = (const float*)d_in[0];
    const void*  ei  = d_in[1];
    const float* W1  = (const float*)d_in[2];
    const float* b1  = (const float*)d_in[3];
    const float* W2  = (const float*)d_in[4];
    const float* b2  = (const float*)d_in[5];
    const float* eps = (const float*)d_in[6];
    float* out = (float*)d_out;

    const int n_edges = in_sizes[1] / 2;

    __nv_bfloat16 *h0hi, *h0lo, *w1th, *w1tl, *w2th, *w2tl;
    cudaGetSymbolAddress((void**)&h0hi, g_h0_hi);
    cudaGetSymbolAddress((void**)&h0lo, g_h0_lo);
    cudaGetSymbolAddress((void**)&w1th, g_w1t_hi);
    cudaGetSymbolAddress((void**)&w1tl, g_w1t_lo);
    cudaGetSymbolAddress((void**)&w2th, g_w2t_hi);
    cudaGetSymbolAddress((void**)&w2tl, g_w2t_lo);

    // 1) prep: bucket + both weight splits in ONE heterogeneous launch
    {
        const int nb_bucket = (n_edges + 1023) / 1024;
        prep_kernel<<<nb_bucket + 512, 256>>>(ei, n_edges, nb_bucket, W1, W2);
    }

    // 2) gather-accumulate (inline overflow) -> split bf16 h0; resets g_cur
    {
        const int wpb = 8;
        gather_kernel<<<(N_NODES + wpb - 1) / wpb, wpb * 32>>>(x, eps, h0hi, h0lo);
    }

    // 3) fused MLP (BM=64, occ 2, cp.async weights, paired-B ldmx4)
    {
        constexpr int SMEM = 114688;   // 112 KB
        cudaFuncSetAttribute(fused_mlp_kernel,
                             cudaFuncAttributeMaxDynamicSharedMemorySize, SMEM);
        const int mtiles = (N_NODES + 63) / 64;   // 782
        fused_mlp_kernel<<<mtiles, 256, SMEM>>>(
            h0hi, h0lo, w1th, w1tl, b1, w2th, w2tl, b2, out, N_NODES);
    }
}